// round 9
// baseline (speedup 1.0000x reference)
#include <cuda_runtime.h>
#include <cuda_fp16.h>
#include <math.h>
#include <stdint.h>

#define NTOT 4096
#define DIM  256
// logits kept in base-2 units: sim_b2 = dot * (log2e / TEMP)
#define SCALE_B2 20.609929155556625f
#define INV_SCALE_B2 (1.0f / 20.609929155556625f)
#define LN2F 0.6931471805599453f
#define NEG_INF -3.4e38f
#define EPS 1e-6f

// ---------------- scratch (device globals; no allocations) ----------------
__device__ __half g_Ah[(size_t)NTOT * DIM];   // A * SCALE_B2, fp16
__device__ __half g_Bh[(size_t)NTOT * DIM];   // B, fp16
// partials laid out [i][p] for coalesced merge reads
__device__ float g_rpm[NTOT * 32];
__device__ float g_rps[NTOT * 32];
__device__ int   g_rpa[NTOT * 32];
__device__ float g_cpm[NTOT * 32];
__device__ float g_cps[NTOT * 32];
__device__ float g_diag[NTOT];     // diag logit (base-2)
__device__ int   g_hard[NTOT];
__device__ float g_hardv[NTOT];    // hard-neg logit value (base-2)
__device__ float g_nA[NTOT], g_sA[NTOT], g_nB[NTOT], g_sB[NTOT];
__device__ float g_terms[4 * NTOT];
__device__ unsigned int g_cnt = 0;
__device__ int g_flag[32];         // per-rowblock conversion-ready flags

// ---------------- helpers ----------------
__device__ __forceinline__ uint32_t smem_u32(const void* p) {
    uint32_t a;
    asm("{ .reg .u64 t; cvta.to.shared.u64 t, %1; cvt.u32.u64 %0, t; }" : "=r"(a) : "l"(p));
    return a;
}
__device__ __forceinline__ float ex2pair(float x, float y) {
    __half2 h = __floats2half2_rn(x, y);
    uint32_t hi = *reinterpret_cast<uint32_t*>(&h);
    uint32_t ro;
    asm("ex2.approx.f16x2 %0, %1;" : "=r"(ro) : "r"(hi));
    __half2 e = *reinterpret_cast<__half2*>(&ro);
    float2 f = __half22float2(e);
    return f.x + f.y;
}
#define LDMX4(r0, r1, r2, r3, addr) \
    asm volatile("ldmatrix.sync.aligned.m8n8.x4.shared.b16 {%0,%1,%2,%3}, [%4];" \
        : "=r"(r0), "=r"(r1), "=r"(r2), "=r"(r3) : "r"(addr))

#define MMA_F16(c, a, b) \
    asm volatile("mma.sync.aligned.m16n8k16.row.col.f32.f16.f16.f32 " \
        "{%0,%1,%2,%3}, {%4,%5,%6,%7}, {%8,%9}, {%0,%1,%2,%3};" \
        : "+f"((c)[0]), "+f"((c)[1]), "+f"((c)[2]), "+f"((c)[3]) \
        : "r"((a)[0]), "r"((a)[1]), "r"((a)[2]), "r"((a)[3]), "r"((b)[0]), "r"((b)[1]))

// ---------------- fused convert + GEMM + register-resident tile reductions ----
#define ROWB 144u
#define OP_SZ (128u * ROWB)
#define STG_SZ (2u * OP_SZ)
#define SMEM_GEMM (2 * STG_SZ)

__global__ __launch_bounds__(256, 2) void gemm_fused(const float* __restrict__ A,
                                                     const float* __restrict__ B) {
    extern __shared__ char smem[];
    const uint32_t sb = smem_u32(smem);
    const int tid = threadIdx.x;
    const int lid = tid & 31;
    const int wid = tid >> 5;
    const int warpM = wid >> 2;
    const int warpN = wid & 3;
    const int quad  = lid & 3;
    const int qrow  = lid >> 2;

    // diagonal-first remap: bids 0..31 = diagonal tiles (producers)
    const int bid = blockIdx.x;
    int bx, by;
    if (bid < 32) { bx = bid; by = bid; }
    else {
        int q = bid - 32;
        by = q / 31;
        int r = q - by * 31;
        bx = (r < by) ? r : r + 1;
    }
    const int rowBase = by * 128;
    const int colBase = bx * 128;

    if (bid < 32) {
        // ---- convert this 128-row block of A and B (warp-per-row, 16 rows/warp) ----
#pragma unroll 4
        for (int rr = 0; rr < 16; rr++) {
            const int w = rowBase + wid * 16 + rr;
            const float4* pa = (const float4*)(A + (size_t)w * DIM);
            const float4* pb = (const float4*)(B + (size_t)w * DIM);
            float4 a0 = pa[lid * 2], a1 = pa[lid * 2 + 1];
            float4 b0 = pb[lid * 2], b1 = pb[lid * 2 + 1];
            __half ha[8] = { __float2half_rn(a0.x * SCALE_B2), __float2half_rn(a0.y * SCALE_B2),
                             __float2half_rn(a0.z * SCALE_B2), __float2half_rn(a0.w * SCALE_B2),
                             __float2half_rn(a1.x * SCALE_B2), __float2half_rn(a1.y * SCALE_B2),
                             __float2half_rn(a1.z * SCALE_B2), __float2half_rn(a1.w * SCALE_B2) };
            __half hb[8] = { __float2half_rn(b0.x), __float2half_rn(b0.y),
                             __float2half_rn(b0.z), __float2half_rn(b0.w),
                             __float2half_rn(b1.x), __float2half_rn(b1.y),
                             __float2half_rn(b1.z), __float2half_rn(b1.w) };
            *(uint4*)(g_Ah + (size_t)w * DIM + lid * 8) = *(uint4*)ha;
            *(uint4*)(g_Bh + (size_t)w * DIM + lid * 8) = *(uint4*)hb;

            float na = a0.x * a0.x + a0.y * a0.y + a0.z * a0.z + a0.w * a0.w
                     + a1.x * a1.x + a1.y * a1.y + a1.z * a1.z + a1.w * a1.w;
            float sa = a0.x + a0.y + a0.z + a0.w + a1.x + a1.y + a1.z + a1.w;
            float nb = b0.x * b0.x + b0.y * b0.y + b0.z * b0.z + b0.w * b0.w
                     + b1.x * b1.x + b1.y * b1.y + b1.z * b1.z + b1.w * b1.w;
            float sbv = b0.x + b0.y + b0.z + b0.w + b1.x + b1.y + b1.z + b1.w;
#pragma unroll
            for (int o = 16; o > 0; o >>= 1) {
                na += __shfl_xor_sync(0xffffffff, na, o);
                sa += __shfl_xor_sync(0xffffffff, sa, o);
                nb += __shfl_xor_sync(0xffffffff, nb, o);
                sbv += __shfl_xor_sync(0xffffffff, sbv, o);
            }
            if (lid == 0) { g_nA[w] = na; g_sA[w] = sa; g_nB[w] = nb; g_sB[w] = sbv; }
        }
        __syncthreads();
        if (tid == 0) {
            __threadfence();
            atomicExch(&g_flag[by], 1);
        }
    } else {
        // ---- wait for producer blocks ----
        if (tid == 0) {
            while (atomicAdd(&g_flag[by], 0) == 0) { }
            while (atomicAdd(&g_flag[bx], 0) == 0) { }
            __threadfence();
        }
        __syncthreads();
    }

    const __half* ga = g_Ah + (size_t)rowBase * DIM;
    const __half* gb = g_Bh + (size_t)colBase * DIM;

    float c[4][4][4];
#pragma unroll
    for (int mf = 0; mf < 4; mf++)
#pragma unroll
        for (int nf = 0; nf < 4; nf++)
#pragma unroll
            for (int r = 0; r < 4; r++) c[mf][nf][r] = 0.f;

    auto load_chunk = [&](int kk, int s) {
        uint32_t aB = sb + s * STG_SZ;
        uint32_t bB = aB + OP_SZ;
#pragma unroll
        for (int i = 0; i < 4; i++) {
            int cc = tid + i * 256;
            int r = cc >> 3, q = cc & 7;
            const void* sa = ga + (size_t)r * DIM + kk * 64 + q * 8;
            asm volatile("cp.async.cg.shared.global [%0], [%1], 16;"
                         :: "r"(aB + r * ROWB + q * 16), "l"(sa));
            const void* sbp = gb + (size_t)r * DIM + kk * 64 + q * 8;
            asm volatile("cp.async.cg.shared.global [%0], [%1], 16;"
                         :: "r"(bB + r * ROWB + q * 16), "l"(sbp));
        }
        asm volatile("cp.async.commit_group;");
    };

    load_chunk(0, 0);
    load_chunk(1, 1);

#pragma unroll
    for (int kk = 0; kk < 4; kk++) {
        const int s = kk & 1;
        if (kk < 3) asm volatile("cp.async.wait_group 1;");
        else        asm volatile("cp.async.wait_group 0;");
        __syncthreads();

        const uint32_t aOff = sb + s * STG_SZ;
        const uint32_t bOff = aOff + OP_SZ;
#pragma unroll
        for (int k2 = 0; k2 < 4; k2++) {
            uint32_t a[4][4];
            const int arow = warpM * 64 + (lid & 15);
            const uint32_t akb = (uint32_t)(k2 * 32 + (lid >> 4) * 16);
#pragma unroll
            for (int mf = 0; mf < 4; mf++)
                LDMX4(a[mf][0], a[mf][1], a[mf][2], a[mf][3],
                      aOff + (uint32_t)(arow + mf * 16) * ROWB + akb);
            uint32_t b[4][2];
            const int nrow = warpN * 32 + ((lid >> 4) << 3) + (lid & 7);
            const uint32_t bkb = (uint32_t)(k2 * 32 + (((lid >> 3) & 1) << 4));
#pragma unroll
            for (int bp = 0; bp < 2; bp++) {
                uint32_t r0, r1, r2, r3;
                LDMX4(r0, r1, r2, r3, bOff + (uint32_t)(nrow + bp * 16) * ROWB + bkb);
                b[2 * bp][0] = r0;     b[2 * bp][1] = r1;
                b[2 * bp + 1][0] = r2; b[2 * bp + 1][1] = r3;
            }
#pragma unroll
            for (int mf = 0; mf < 4; mf++)
#pragma unroll
                for (int nf = 0; nf < 4; nf++)
                    MMA_F16(c[mf][nf], a[mf], b[nf]);
        }
        __syncthreads();
        if (kk + 2 < 4) load_chunk(kk + 2, s);
    }

    // ================= register-resident epilogue (R7 structure) =================
    float* sRowM   = (float*)smem;
    int*   sRowA   = (int*)  (smem + 2048);
    float* sRowS   = (float*)(smem + 4096);
    float* sColM   = (float*)(smem + 6144);
    float* sColS   = (float*)(smem + 7168);
    float* sRowMax = (float*)(smem + 8192);
    float* sColMax = (float*)(smem + 8704);
    float* sHM     = (float*)(smem + 9216);
    int*   sHA     = (int*)  (smem + 11264);

    const bool diag = (bx == by);

    // ---- phase A: warp-level row (max,arg) and col max ----
    float rm[8]; int ra[8];
#pragma unroll
    for (int mf = 0; mf < 4; mf++)
#pragma unroll
        for (int h = 0; h < 2; h++) {
            float m = NEG_INF; int a = 0;
#pragma unroll
            for (int nf = 0; nf < 4; nf++) {
                float v0 = c[mf][nf][h * 2], v1 = c[mf][nf][h * 2 + 1];
                int lc = nf * 8 + quad * 2;
                if (v0 > m) { m = v0; a = lc; }
                if (v1 > m) { m = v1; a = lc + 1; }
            }
            rm[mf * 2 + h] = m; ra[mf * 2 + h] = a;
        }
#pragma unroll
    for (int idx = 0; idx < 8; idx++)
#pragma unroll
        for (int o = 1; o < 4; o <<= 1) {
            float m2 = __shfl_xor_sync(0xffffffff, rm[idx], o);
            int   a2 = __shfl_xor_sync(0xffffffff, ra[idx], o);
            if (m2 > rm[idx] || (m2 == rm[idx] && a2 < ra[idx])) { rm[idx] = m2; ra[idx] = a2; }
        }
    if (quad == 0) {
#pragma unroll
        for (int idx = 0; idx < 8; idx++) {
            int row = warpM * 64 + (idx >> 1) * 16 + (idx & 1) * 8 + qrow;
            sRowM[warpN * 128 + row] = rm[idx];
            sRowA[warpN * 128 + row] = warpN * 32 + ra[idx];
        }
    }

    float cmx[8];
#pragma unroll
    for (int nf = 0; nf < 4; nf++)
#pragma unroll
        for (int p = 0; p < 2; p++) {
            float m = NEG_INF;
#pragma unroll
            for (int mf = 0; mf < 4; mf++)
                m = fmaxf(m, fmaxf(c[mf][nf][p], c[mf][nf][2 + p]));
            cmx[nf * 2 + p] = m;
        }
#pragma unroll
    for (int idx = 0; idx < 8; idx++)
#pragma unroll
        for (int o = 4; o < 32; o <<= 1)
            cmx[idx] = fmaxf(cmx[idx], __shfl_xor_sync(0xffffffff, cmx[idx], o));
    if (qrow == 0) {
#pragma unroll
        for (int idx = 0; idx < 8; idx++) {
            int col = warpN * 32 + (idx >> 1) * 8 + quad * 2 + (idx & 1);
            sColM[warpM * 128 + col] = cmx[idx];
        }
    }

    if (diag) {
        float hm[8]; int hha[8];
#pragma unroll
        for (int mf = 0; mf < 4; mf++)
#pragma unroll
            for (int h = 0; h < 2; h++) {
                int lr = warpM * 64 + mf * 16 + h * 8 + qrow;
                float m = NEG_INF; int a = 0;
#pragma unroll
                for (int nf = 0; nf < 4; nf++)
#pragma unroll
                    for (int p = 0; p < 2; p++) {
                        int lc = warpN * 32 + nf * 8 + quad * 2 + p;
                        float v = c[mf][nf][h * 2 + p];
                        if (lc == lr) g_diag[rowBase + lr] = v;
                        else if (v > m) { m = v; a = lc; }
                    }
                hm[mf * 2 + h] = m; hha[mf * 2 + h] = a;
            }
#pragma unroll
        for (int idx = 0; idx < 8; idx++)
#pragma unroll
            for (int o = 1; o < 4; o <<= 1) {
                float m2 = __shfl_xor_sync(0xffffffff, hm[idx], o);
                int   a2 = __shfl_xor_sync(0xffffffff, hha[idx], o);
                if (m2 > hm[idx] || (m2 == hm[idx] && a2 < hha[idx])) { hm[idx] = m2; hha[idx] = a2; }
            }
        if (quad == 0) {
#pragma unroll
            for (int idx = 0; idx < 8; idx++) {
                int row = warpM * 64 + (idx >> 1) * 16 + (idx & 1) * 8 + qrow;
                sHM[warpN * 128 + row] = hm[idx];
                sHA[warpN * 128 + row] = hha[idx];
            }
        }
    }
    __syncthreads();

    // ---- phase B: cross-warp combine of maxes ----
    if (tid < 128) {
        const int r = tid;
        float m = sRowM[r]; int a = sRowA[r];
#pragma unroll
        for (int w = 1; w < 4; w++) {
            float m2 = sRowM[w * 128 + r];
            if (m2 > m) { m = m2; a = sRowA[w * 128 + r]; }
        }
        sRowMax[r] = m;
        g_rpm[(size_t)(rowBase + r) * 32 + bx] = m;
        g_rpa[(size_t)(rowBase + r) * 32 + bx] = colBase + a;
        if (diag) {
            float hm = sHM[r]; int hha = sHA[r];
#pragma unroll
            for (int w = 1; w < 4; w++) {
                float m2 = sHM[w * 128 + r];
                if (m2 > hm) { hm = m2; hha = sHA[w * 128 + r]; }
            }
            g_hard[rowBase + r]  = colBase + hha;
            g_hardv[rowBase + r] = hm;
        }
    } else {
        const int cI = tid - 128;
        float m = fmaxf(sColM[cI], sColM[128 + cI]);
        sColMax[cI] = m;
        g_cpm[(size_t)(colBase + cI) * 32 + by] = m;
    }
    __syncthreads();

    // ---- phase C: sums from registers ----
    float rs[8];
#pragma unroll
    for (int mf = 0; mf < 4; mf++)
#pragma unroll
        for (int h = 0; h < 2; h++) {
            const int row = warpM * 64 + mf * 16 + h * 8 + qrow;
            const float M = sRowMax[row];
            float s = 0.f;
#pragma unroll
            for (int nf = 0; nf < 4; nf++)
                s += ex2pair(c[mf][nf][h * 2] - M, c[mf][nf][h * 2 + 1] - M);
            rs[mf * 2 + h] = s;
        }
#pragma unroll
    for (int idx = 0; idx < 8; idx++)
#pragma unroll
        for (int o = 1; o < 4; o <<= 1)
            rs[idx] += __shfl_xor_sync(0xffffffff, rs[idx], o);
    if (quad == 0) {
#pragma unroll
        for (int idx = 0; idx < 8; idx++) {
            int row = warpM * 64 + (idx >> 1) * 16 + (idx & 1) * 8 + qrow;
            sRowS[warpN * 128 + row] = rs[idx];
        }
    }

    float cs[8];
#pragma unroll
    for (int nf = 0; nf < 4; nf++)
#pragma unroll
        for (int p = 0; p < 2; p++) {
            const int col = warpN * 32 + nf * 8 + quad * 2 + p;
            const float M = sColMax[col];
            float s = 0.f;
#pragma unroll
            for (int mf = 0; mf < 4; mf++)
                s += ex2pair(c[mf][nf][p] - M, c[mf][nf][2 + p] - M);
            cs[nf * 2 + p] = s;
        }
#pragma unroll
    for (int idx = 0; idx < 8; idx++)
#pragma unroll
        for (int o = 4; o < 32; o <<= 1)
            cs[idx] += __shfl_xor_sync(0xffffffff, cs[idx], o);
    if (qrow == 0) {
#pragma unroll
        for (int idx = 0; idx < 8; idx++) {
            int col = warpN * 32 + (idx >> 1) * 8 + quad * 2 + (idx & 1);
            sColS[warpM * 128 + col] = cs[idx];
        }
    }
    __syncthreads();

    // ---- phase D: final combine + global store ----
    if (tid < 128) {
        const int r = tid;
        g_rps[(size_t)(rowBase + r) * 32 + bx] =
            sRowS[r] + sRowS[128 + r] + sRowS[256 + r] + sRowS[384 + r];
    } else {
        const int cI = tid - 128;
        g_cps[(size_t)(colBase + cI) * 32 + by] = sColS[cI] + sColS[128 + cI];
    }
}

// ---------------- fused merge (row + col + algebraic triplet) + last-block final ----
__global__ void merge_all(float* __restrict__ out) {
    const int i = blockIdx.x * 8 + (threadIdx.x >> 5);
    const int lane = threadIdx.x & 31;

    float m0 = g_rpm[(size_t)i * 32 + lane];
    float s0 = g_rps[(size_t)i * 32 + lane];
    int   a0 = g_rpa[(size_t)i * 32 + lane];
    float bm = m0; int bp = lane; int ba = a0;
#pragma unroll
    for (int o = 16; o > 0; o >>= 1) {
        float m2 = __shfl_xor_sync(0xffffffff, bm, o);
        int   p2 = __shfl_xor_sync(0xffffffff, bp, o);
        int   a2 = __shfl_xor_sync(0xffffffff, ba, o);
        if (m2 > bm || (m2 == bm && p2 < bp)) { bm = m2; bp = p2; ba = a2; }
    }
    float se = s0 * exp2f(m0 - bm);
#pragma unroll
    for (int o = 16; o > 0; o >>= 1) se += __shfl_xor_sync(0xffffffff, se, o);

    float cm0 = g_cpm[(size_t)i * 32 + lane];
    float cs0 = g_cps[(size_t)i * 32 + lane];
    float cm = cm0;
#pragma unroll
    for (int o = 16; o > 0; o >>= 1) cm = fmaxf(cm, __shfl_xor_sync(0xffffffff, cm, o));
    float cse = cs0 * exp2f(cm0 - cm);
#pragma unroll
    for (int o = 16; o > 0; o >>= 1) cse += __shfl_xor_sync(0xffffffff, cse, o);

    if (lane == 0) {
        float d = g_diag[i];
        int j = g_hard[i];
        float dotp = d * INV_SCALE_B2;
        float dotn = g_hardv[i] * INV_SCALE_B2;
        float na = g_nA[i], sa = g_sA[i];
        float ps = na + g_nB[i] - 2.f * dotp + 2.f * EPS * (sa - g_sB[i]) + DIM * EPS * EPS;
        float ns = na + g_nB[j] - 2.f * dotn + 2.f * EPS * (sa - g_sB[j]) + DIM * EPS * EPS;
        float trip = sqrtf(fmaxf(ps, 0.f)) - sqrtf(fmaxf(ns, 0.f)) + 0.5f;
        g_terms[i]            = (bm + __log2f(se) - d) * LN2F;
        g_terms[NTOT + i]     = (cm + __log2f(cse) - d) * LN2F;
        g_terms[2 * NTOT + i] = trip > 0.f ? trip : 0.f;
        g_terms[3 * NTOT + i] = (ba == i) ? 1.0f : 0.0f;
    }

    __shared__ unsigned int s_last;
    __syncthreads();
    if (threadIdx.x == 0) {
        __threadfence();
        s_last = (atomicAdd(&g_cnt, 1u) == gridDim.x - 1) ? 1u : 0u;
    }
    __syncthreads();
    if (s_last) {
        __threadfence();
        if (threadIdx.x == 0) g_cnt = 0;
        if (threadIdx.x < 32) g_flag[threadIdx.x] = 0;   // reset for next replay
        float t0 = 0.f, t1 = 0.f, t2 = 0.f, t3 = 0.f;
        for (int jj = threadIdx.x; jj < NTOT; jj += 256) {
            t0 += g_terms[jj];
            t1 += g_terms[NTOT + jj];
            t2 += g_terms[2 * NTOT + jj];
            t3 += g_terms[3 * NTOT + jj];
        }
#pragma unroll
        for (int o = 16; o > 0; o >>= 1) {
            t0 += __shfl_xor_sync(0xffffffff, t0, o);
            t1 += __shfl_xor_sync(0xffffffff, t1, o);
            t2 += __shfl_xor_sync(0xffffffff, t2, o);
            t3 += __shfl_xor_sync(0xffffffff, t3, o);
        }
        __shared__ float red[4][8];
        const int w = threadIdx.x >> 5;
        if (lane == 0) { red[0][w] = t0; red[1][w] = t1; red[2][w] = t2; red[3][w] = t3; }
        __syncthreads();
        if (threadIdx.x == 0) {
            float s4[4];
            for (int cc = 0; cc < 4; cc++) {
                float s = 0.f;
                for (int ww = 0; ww < 8; ww++) s += red[cc][ww];
                s4[cc] = s;
            }
            float info = 0.5f * (s4[0] + s4[1]) / (float)NTOT;
            float trip = s4[2] / (float)NTOT;
            float acc  = s4[3] / (float)NTOT;
            out[0] = info + 0.1f * trip;
            out[1] = info;
            out[2] = trip;
            out[3] = acc;
        }
    }
}

extern "C" void kernel_launch(void* const* d_in, const int* in_sizes, int n_in,
                              void* d_out, int out_size) {
    const float* A = (const float*)d_in[0];
    const float* B = (const float*)d_in[1];
    float* out = (float*)d_out;

    static bool configured = false;
    if (!configured) {
        cudaFuncSetAttribute(gemm_fused, cudaFuncAttributeMaxDynamicSharedMemorySize,
                             SMEM_GEMM);
        configured = true;
    }

    gemm_fused<<<1024, 256, SMEM_GEMM>>>(A, B);
    merge_all<<<512, 256>>>(out);
}

// round 10
// speedup vs baseline: 1.1189x; 1.1189x over previous
#include <cuda_runtime.h>
#include <cuda_fp16.h>
#include <math.h>
#include <stdint.h>

#define NTOT 4096
#define DIM  256
// logits kept in base-2 units: sim_b2 = dot * (log2e / TEMP)
#define SCALE_B2 20.609929155556625f
#define INV_SCALE_B2 (1.0f / 20.609929155556625f)
#define LN2F 0.6931471805599453f
#define NEG_INF -3.4e38f
#define EPS 1e-6f

// ---------------- scratch (device globals; no allocations) ----------------
__device__ __half g_Ah[(size_t)NTOT * DIM];   // A * SCALE_B2, fp16
__device__ __half g_Bh[(size_t)NTOT * DIM];   // B, fp16
// partials laid out [i][p] for coalesced merge reads
__device__ float g_rpm[NTOT * 32];
__device__ float g_rps[NTOT * 32];
__device__ int   g_rpa[NTOT * 32];
__device__ float g_cpm[NTOT * 32];
__device__ float g_cps[NTOT * 32];
__device__ float g_diag[NTOT];     // diag logit (base-2)
__device__ int   g_hard[NTOT];
__device__ float g_hardv[NTOT];    // hard-neg logit value (base-2)
__device__ float g_nA[NTOT], g_sA[NTOT], g_nB[NTOT], g_sB[NTOT];
__device__ float g_terms[4 * NTOT];
__device__ unsigned int g_cnt = 0;

// ---------------- helpers ----------------
__device__ __forceinline__ uint32_t smem_u32(const void* p) {
    uint32_t a;
    asm("{ .reg .u64 t; cvta.to.shared.u64 t, %1; cvt.u32.u64 %0, t; }" : "=r"(a) : "l"(p));
    return a;
}
__device__ __forceinline__ float ex2pair(float x, float y) {
    __half2 h = __floats2half2_rn(x, y);
    uint32_t hi = *reinterpret_cast<uint32_t*>(&h);
    uint32_t ro;
    asm("ex2.approx.f16x2 %0, %1;" : "=r"(ro) : "r"(hi));
    __half2 e = *reinterpret_cast<__half2*>(&ro);
    float2 f = __half22float2(e);
    return f.x + f.y;
}
#define LDMX4(r0, r1, r2, r3, addr) \
    asm volatile("ldmatrix.sync.aligned.m8n8.x4.shared.b16 {%0,%1,%2,%3}, [%4];" \
        : "=r"(r0), "=r"(r1), "=r"(r2), "=r"(r3) : "r"(addr))

#define MMA_F16(c, a, b) \
    asm volatile("mma.sync.aligned.m16n8k16.row.col.f32.f16.f16.f32 " \
        "{%0,%1,%2,%3}, {%4,%5,%6,%7}, {%8,%9}, {%0,%1,%2,%3};" \
        : "+f"((c)[0]), "+f"((c)[1]), "+f"((c)[2]), "+f"((c)[3]) \
        : "r"((a)[0]), "r"((a)[1]), "r"((a)[2]), "r"((a)[3]), "r"((b)[0]), "r"((b)[1]))

// ---------------- split: fp32 -> fp16, warp per matrix-row (8192 warps) -------
__global__ void split_f16(const float* __restrict__ A, const float* __restrict__ B) {
    const int w = blockIdx.x * 8 + (threadIdx.x >> 5);   // 0..8191
    const int lane = threadIdx.x & 31;
    const int row = w & 4095;
    if (w < 4096) {
        const float4* pa = (const float4*)(A + (size_t)row * DIM);
        float4 a0 = pa[lane * 2], a1 = pa[lane * 2 + 1];
        __half ha[8] = { __float2half_rn(a0.x * SCALE_B2), __float2half_rn(a0.y * SCALE_B2),
                         __float2half_rn(a0.z * SCALE_B2), __float2half_rn(a0.w * SCALE_B2),
                         __float2half_rn(a1.x * SCALE_B2), __float2half_rn(a1.y * SCALE_B2),
                         __float2half_rn(a1.z * SCALE_B2), __float2half_rn(a1.w * SCALE_B2) };
        *(uint4*)(g_Ah + (size_t)row * DIM + lane * 8) = *(uint4*)ha;
        float na = a0.x * a0.x + a0.y * a0.y + a0.z * a0.z + a0.w * a0.w
                 + a1.x * a1.x + a1.y * a1.y + a1.z * a1.z + a1.w * a1.w;
        float sa = a0.x + a0.y + a0.z + a0.w + a1.x + a1.y + a1.z + a1.w;
#pragma unroll
        for (int o = 16; o > 0; o >>= 1) {
            na += __shfl_xor_sync(0xffffffff, na, o);
            sa += __shfl_xor_sync(0xffffffff, sa, o);
        }
        if (lane == 0) { g_nA[row] = na; g_sA[row] = sa; }
    } else {
        const float4* pb = (const float4*)(B + (size_t)row * DIM);
        float4 b0 = pb[lane * 2], b1 = pb[lane * 2 + 1];
        __half hb[8] = { __float2half_rn(b0.x), __float2half_rn(b0.y),
                         __float2half_rn(b0.z), __float2half_rn(b0.w),
                         __float2half_rn(b1.x), __float2half_rn(b1.y),
                         __float2half_rn(b1.z), __float2half_rn(b1.w) };
        *(uint4*)(g_Bh + (size_t)row * DIM + lane * 8) = *(uint4*)hb;
        float nb = b0.x * b0.x + b0.y * b0.y + b0.z * b0.z + b0.w * b0.w
                 + b1.x * b1.x + b1.y * b1.y + b1.z * b1.z + b1.w * b1.w;
        float sb = b0.x + b0.y + b0.z + b0.w + b1.x + b1.y + b1.z + b1.w;
#pragma unroll
        for (int o = 16; o > 0; o >>= 1) {
            nb += __shfl_xor_sync(0xffffffff, nb, o);
            sb += __shfl_xor_sync(0xffffffff, sb, o);
        }
        if (lane == 0) { g_nB[row] = nb; g_sB[row] = sb; }
    }
}

// ---------------- fused GEMM (4-stage, K=32 chunks) + register epilogue -------
#define ROWB 80u                        // 32 fp16 = 64B + 16B pad
#define OP_SZ (128u * ROWB)             // 10240
#define STG_SZ (2u * OP_SZ)             // 20480
#define SMEM_GEMM (4 * STG_SZ)          // 81920

__global__ __launch_bounds__(256, 2) void gemm_fused() {
    extern __shared__ char smem[];
    const uint32_t sb = smem_u32(smem);
    const int tid = threadIdx.x;
    const int lid = tid & 31;
    const int wid = tid >> 5;
    const int warpM = wid >> 2;
    const int warpN = wid & 3;
    const int quad  = lid & 3;
    const int qrow  = lid >> 2;
    const int rowBase = blockIdx.y * 128;
    const int colBase = blockIdx.x * 128;

    const __half* ga = g_Ah + (size_t)rowBase * DIM;
    const __half* gb = g_Bh + (size_t)colBase * DIM;

    float c[4][4][4];
#pragma unroll
    for (int mf = 0; mf < 4; mf++)
#pragma unroll
        for (int nf = 0; nf < 4; nf++)
#pragma unroll
            for (int r = 0; r < 4; r++) c[mf][nf][r] = 0.f;

    // chunk = K=32 slice: per operand 128 rows x 4 16B-chunks = 512; 1024 total
    auto load_chunk = [&](int kk, int s) {
        const uint32_t base = sb + s * STG_SZ;
#pragma unroll
        for (int i = 0; i < 4; i++) {
            int cc = tid + i * 256;          // 0..1023
            int o  = cc >> 9;                // 0 = A, 1 = B
            int idx = cc & 511;
            int r = idx >> 2, q = idx & 3;
            const __half* src = (o ? gb : ga) + (size_t)r * DIM + kk * 32 + q * 8;
            asm volatile("cp.async.cg.shared.global [%0], [%1], 16;"
                         :: "r"(base + o * OP_SZ + (uint32_t)(r * ROWB + q * 16)), "l"(src));
        }
        asm volatile("cp.async.commit_group;");
    };

    load_chunk(0, 0);
    load_chunk(1, 1);
    load_chunk(2, 2);

#pragma unroll
    for (int kk = 0; kk < 8; kk++) {
        const int s = kk & 3;
        if (kk <= 5)      asm volatile("cp.async.wait_group 2;");
        else if (kk == 6) asm volatile("cp.async.wait_group 1;");
        else              asm volatile("cp.async.wait_group 0;");
        __syncthreads();   // data visible + all warps done reading stage (kk-1)&3

        const uint32_t aOff = sb + s * STG_SZ;
        const uint32_t bOff = aOff + OP_SZ;
#pragma unroll
        for (int k2 = 0; k2 < 2; k2++) {
            uint32_t a[4][4];
            const int arow = warpM * 64 + (lid & 15);
            const uint32_t akb = (uint32_t)(k2 * 32 + (lid >> 4) * 16);
#pragma unroll
            for (int mf = 0; mf < 4; mf++)
                LDMX4(a[mf][0], a[mf][1], a[mf][2], a[mf][3],
                      aOff + (uint32_t)(arow + mf * 16) * ROWB + akb);
            uint32_t b[4][2];
            const int nrow = warpN * 32 + ((lid >> 4) << 3) + (lid & 7);
            const uint32_t bkb = (uint32_t)(k2 * 32 + (((lid >> 3) & 1) << 4));
#pragma unroll
            for (int bp = 0; bp < 2; bp++) {
                uint32_t r0, r1, r2, r3;
                LDMX4(r0, r1, r2, r3, bOff + (uint32_t)(nrow + bp * 16) * ROWB + bkb);
                b[2 * bp][0] = r0;     b[2 * bp][1] = r1;
                b[2 * bp + 1][0] = r2; b[2 * bp + 1][1] = r3;
            }
#pragma unroll
            for (int mf = 0; mf < 4; mf++)
#pragma unroll
                for (int nf = 0; nf < 4; nf++)
                    MMA_F16(c[mf][nf], a[mf], b[nf]);
        }
        if (kk + 3 < 8) load_chunk(kk + 3, (kk + 3) & 3);
    }

    // ================= register-resident epilogue (R7 structure) =================
    float* sRowM   = (float*)smem;
    int*   sRowA   = (int*)  (smem + 2048);
    float* sRowS   = (float*)(smem + 4096);
    float* sColM   = (float*)(smem + 6144);
    float* sColS   = (float*)(smem + 7168);
    float* sRowMax = (float*)(smem + 8192);
    float* sColMax = (float*)(smem + 8704);
    float* sHM     = (float*)(smem + 9216);
    int*   sHA     = (int*)  (smem + 11264);

    const bool diag = (blockIdx.x == blockIdx.y);

    // ---- phase A: warp-level row (max,arg) and col max ----
    float rm[8]; int ra[8];
#pragma unroll
    for (int mf = 0; mf < 4; mf++)
#pragma unroll
        for (int h = 0; h < 2; h++) {
            float m = NEG_INF; int a = 0;
#pragma unroll
            for (int nf = 0; nf < 4; nf++) {
                float v0 = c[mf][nf][h * 2], v1 = c[mf][nf][h * 2 + 1];
                int lc = nf * 8 + quad * 2;
                if (v0 > m) { m = v0; a = lc; }
                if (v1 > m) { m = v1; a = lc + 1; }
            }
            rm[mf * 2 + h] = m; ra[mf * 2 + h] = a;
        }
#pragma unroll
    for (int idx = 0; idx < 8; idx++)
#pragma unroll
        for (int o = 1; o < 4; o <<= 1) {
            float m2 = __shfl_xor_sync(0xffffffff, rm[idx], o);
            int   a2 = __shfl_xor_sync(0xffffffff, ra[idx], o);
            if (m2 > rm[idx] || (m2 == rm[idx] && a2 < ra[idx])) { rm[idx] = m2; ra[idx] = a2; }
        }
    if (quad == 0) {
#pragma unroll
        for (int idx = 0; idx < 8; idx++) {
            int row = warpM * 64 + (idx >> 1) * 16 + (idx & 1) * 8 + qrow;
            sRowM[warpN * 128 + row] = rm[idx];
            sRowA[warpN * 128 + row] = warpN * 32 + ra[idx];
        }
    }

    float cmx[8];
#pragma unroll
    for (int nf = 0; nf < 4; nf++)
#pragma unroll
        for (int p = 0; p < 2; p++) {
            float m = NEG_INF;
#pragma unroll
            for (int mf = 0; mf < 4; mf++)
                m = fmaxf(m, fmaxf(c[mf][nf][p], c[mf][nf][2 + p]));
            cmx[nf * 2 + p] = m;
        }
#pragma unroll
    for (int idx = 0; idx < 8; idx++)
#pragma unroll
        for (int o = 4; o < 32; o <<= 1)
            cmx[idx] = fmaxf(cmx[idx], __shfl_xor_sync(0xffffffff, cmx[idx], o));
    if (qrow == 0) {
#pragma unroll
        for (int idx = 0; idx < 8; idx++) {
            int col = warpN * 32 + (idx >> 1) * 8 + quad * 2 + (idx & 1);
            sColM[warpM * 128 + col] = cmx[idx];
        }
    }

    if (diag) {
        float hm[8]; int hha[8];
#pragma unroll
        for (int mf = 0; mf < 4; mf++)
#pragma unroll
            for (int h = 0; h < 2; h++) {
                int lr = warpM * 64 + mf * 16 + h * 8 + qrow;
                float m = NEG_INF; int a = 0;
#pragma unroll
                for (int nf = 0; nf < 4; nf++)
#pragma unroll
                    for (int p = 0; p < 2; p++) {
                        int lc = warpN * 32 + nf * 8 + quad * 2 + p;
                        float v = c[mf][nf][h * 2 + p];
                        if (lc == lr) g_diag[rowBase + lr] = v;
                        else if (v > m) { m = v; a = lc; }
                    }
                hm[mf * 2 + h] = m; hha[mf * 2 + h] = a;
            }
#pragma unroll
        for (int idx = 0; idx < 8; idx++)
#pragma unroll
            for (int o = 1; o < 4; o <<= 1) {
                float m2 = __shfl_xor_sync(0xffffffff, hm[idx], o);
                int   a2 = __shfl_xor_sync(0xffffffff, hha[idx], o);
                if (m2 > hm[idx] || (m2 == hm[idx] && a2 < hha[idx])) { hm[idx] = m2; hha[idx] = a2; }
            }
        if (quad == 0) {
#pragma unroll
            for (int idx = 0; idx < 8; idx++) {
                int row = warpM * 64 + (idx >> 1) * 16 + (idx & 1) * 8 + qrow;
                sHM[warpN * 128 + row] = hm[idx];
                sHA[warpN * 128 + row] = hha[idx];
            }
        }
    }
    __syncthreads();

    // ---- phase B: cross-warp combine of maxes ----
    if (tid < 128) {
        const int r = tid;
        float m = sRowM[r]; int a = sRowA[r];
#pragma unroll
        for (int w = 1; w < 4; w++) {
            float m2 = sRowM[w * 128 + r];
            if (m2 > m) { m = m2; a = sRowA[w * 128 + r]; }
        }
        sRowMax[r] = m;
        g_rpm[(size_t)(rowBase + r) * 32 + blockIdx.x] = m;
        g_rpa[(size_t)(rowBase + r) * 32 + blockIdx.x] = colBase + a;
        if (diag) {
            float hm = sHM[r]; int hha = sHA[r];
#pragma unroll
            for (int w = 1; w < 4; w++) {
                float m2 = sHM[w * 128 + r];
                if (m2 > hm) { hm = m2; hha = sHA[w * 128 + r]; }
            }
            g_hard[rowBase + r]  = colBase + hha;
            g_hardv[rowBase + r] = hm;
        }
    } else {
        const int cI = tid - 128;
        float m = fmaxf(sColM[cI], sColM[128 + cI]);
        sColMax[cI] = m;
        g_cpm[(size_t)(colBase + cI) * 32 + blockIdx.y] = m;
    }
    __syncthreads();

    // ---- phase C: sums from registers ----
    float rs[8];
#pragma unroll
    for (int mf = 0; mf < 4; mf++)
#pragma unroll
        for (int h = 0; h < 2; h++) {
            const int row = warpM * 64 + mf * 16 + h * 8 + qrow;
            const float M = sRowMax[row];
            float s = 0.f;
#pragma unroll
            for (int nf = 0; nf < 4; nf++)
                s += ex2pair(c[mf][nf][h * 2] - M, c[mf][nf][h * 2 + 1] - M);
            rs[mf * 2 + h] = s;
        }
#pragma unroll
    for (int idx = 0; idx < 8; idx++)
#pragma unroll
        for (int o = 1; o < 4; o <<= 1)
            rs[idx] += __shfl_xor_sync(0xffffffff, rs[idx], o);
    if (quad == 0) {
#pragma unroll
        for (int idx = 0; idx < 8; idx++) {
            int row = warpM * 64 + (idx >> 1) * 16 + (idx & 1) * 8 + qrow;
            sRowS[warpN * 128 + row] = rs[idx];
        }
    }

    float cs[8];
#pragma unroll
    for (int nf = 0; nf < 4; nf++)
#pragma unroll
        for (int p = 0; p < 2; p++) {
            const int col = warpN * 32 + nf * 8 + quad * 2 + p;
            const float M = sColMax[col];
            float s = 0.f;
#pragma unroll
            for (int mf = 0; mf < 4; mf++)
                s += ex2pair(c[mf][nf][p] - M, c[mf][nf][2 + p] - M);
            cs[nf * 2 + p] = s;
        }
#pragma unroll
    for (int idx = 0; idx < 8; idx++)
#pragma unroll
        for (int o = 4; o < 32; o <<= 1)
            cs[idx] += __shfl_xor_sync(0xffffffff, cs[idx], o);
    if (qrow == 0) {
#pragma unroll
        for (int idx = 0; idx < 8; idx++) {
            int col = warpN * 32 + (idx >> 1) * 8 + quad * 2 + (idx & 1);
            sColS[warpM * 128 + col] = cs[idx];
        }
    }
    __syncthreads();

    // ---- phase D: final combine + global store ----
    if (tid < 128) {
        const int r = tid;
        g_rps[(size_t)(rowBase + r) * 32 + blockIdx.x] =
            sRowS[r] + sRowS[128 + r] + sRowS[256 + r] + sRowS[384 + r];
    } else {
        const int cI = tid - 128;
        g_cps[(size_t)(colBase + cI) * 32 + blockIdx.y] = sColS[cI] + sColS[128 + cI];
    }
}

// ---------------- fused merge (row + col + algebraic triplet) + last-block final ----
__global__ void merge_all(float* __restrict__ out) {
    const int i = blockIdx.x * 8 + (threadIdx.x >> 5);
    const int lane = threadIdx.x & 31;

    float m0 = g_rpm[(size_t)i * 32 + lane];
    float s0 = g_rps[(size_t)i * 32 + lane];
    int   a0 = g_rpa[(size_t)i * 32 + lane];
    float bm = m0; int bp = lane; int ba = a0;
#pragma unroll
    for (int o = 16; o > 0; o >>= 1) {
        float m2 = __shfl_xor_sync(0xffffffff, bm, o);
        int   p2 = __shfl_xor_sync(0xffffffff, bp, o);
        int   a2 = __shfl_xor_sync(0xffffffff, ba, o);
        if (m2 > bm || (m2 == bm && p2 < bp)) { bm = m2; bp = p2; ba = a2; }
    }
    float se = s0 * exp2f(m0 - bm);
#pragma unroll
    for (int o = 16; o > 0; o >>= 1) se += __shfl_xor_sync(0xffffffff, se, o);

    float cm0 = g_cpm[(size_t)i * 32 + lane];
    float cs0 = g_cps[(size_t)i * 32 + lane];
    float cm = cm0;
#pragma unroll
    for (int o = 16; o > 0; o >>= 1) cm = fmaxf(cm, __shfl_xor_sync(0xffffffff, cm, o));
    float cse = cs0 * exp2f(cm0 - cm);
#pragma unroll
    for (int o = 16; o > 0; o >>= 1) cse += __shfl_xor_sync(0xffffffff, cse, o);

    if (lane == 0) {
        float d = g_diag[i];
        int j = g_hard[i];
        float dotp = d * INV_SCALE_B2;
        float dotn = g_hardv[i] * INV_SCALE_B2;
        float na = g_nA[i], sa = g_sA[i];
        float ps = na + g_nB[i] - 2.f * dotp + 2.f * EPS * (sa - g_sB[i]) + DIM * EPS * EPS;
        float ns = na + g_nB[j] - 2.f * dotn + 2.f * EPS * (sa - g_sB[j]) + DIM * EPS * EPS;
        float trip = sqrtf(fmaxf(ps, 0.f)) - sqrtf(fmaxf(ns, 0.f)) + 0.5f;
        g_terms[i]            = (bm + __log2f(se) - d) * LN2F;
        g_terms[NTOT + i]     = (cm + __log2f(cse) - d) * LN2F;
        g_terms[2 * NTOT + i] = trip > 0.f ? trip : 0.f;
        g_terms[3 * NTOT + i] = (ba == i) ? 1.0f : 0.0f;
    }

    __shared__ unsigned int s_last;
    __syncthreads();
    if (threadIdx.x == 0) {
        __threadfence();
        s_last = (atomicAdd(&g_cnt, 1u) == gridDim.x - 1) ? 1u : 0u;
    }
    __syncthreads();
    if (s_last) {
        __threadfence();
        if (threadIdx.x == 0) g_cnt = 0;
        float t0 = 0.f, t1 = 0.f, t2 = 0.f, t3 = 0.f;
        for (int jj = threadIdx.x; jj < NTOT; jj += 256) {
            t0 += g_terms[jj];
            t1 += g_terms[NTOT + jj];
            t2 += g_terms[2 * NTOT + jj];
            t3 += g_terms[3 * NTOT + jj];
        }
#pragma unroll
        for (int o = 16; o > 0; o >>= 1) {
            t0 += __shfl_xor_sync(0xffffffff, t0, o);
            t1 += __shfl_xor_sync(0xffffffff, t1, o);
            t2 += __shfl_xor_sync(0xffffffff, t2, o);
            t3 += __shfl_xor_sync(0xffffffff, t3, o);
        }
        __shared__ float red[4][8];
        const int w = threadIdx.x >> 5;
        if (lane == 0) { red[0][w] = t0; red[1][w] = t1; red[2][w] = t2; red[3][w] = t3; }
        __syncthreads();
        if (threadIdx.x == 0) {
            float s4[4];
            for (int cc = 0; cc < 4; cc++) {
                float s = 0.f;
                for (int ww = 0; ww < 8; ww++) s += red[cc][ww];
                s4[cc] = s;
            }
            float info = 0.5f * (s4[0] + s4[1]) / (float)NTOT;
            float trip = s4[2] / (float)NTOT;
            float acc  = s4[3] / (float)NTOT;
            out[0] = info + 0.1f * trip;
            out[1] = info;
            out[2] = trip;
            out[3] = acc;
        }
    }
}

extern "C" void kernel_launch(void* const* d_in, const int* in_sizes, int n_in,
                              void* d_out, int out_size) {
    const float* A = (const float*)d_in[0];
    const float* B = (const float*)d_in[1];
    float* out = (float*)d_out;

    static bool configured = false;
    if (!configured) {
        cudaFuncSetAttribute(gemm_fused, cudaFuncAttributeMaxDynamicSharedMemorySize,
                             SMEM_GEMM);
        configured = true;
    }

    split_f16<<<1024, 256>>>(A, B);
    gemm_fused<<<dim3(32, 32), 256, SMEM_GEMM>>>();
    merge_all<<<512, 256>>>(out);
}